// round 6
// baseline (speedup 1.0000x reference)
#include <cuda_runtime.h>
#include <cstdint>

// Problem constants
#define NN      8192
#define DD      128
#define BT      128
#define NT      (NN / BT)          // 64
#define NUNITS  (NT * NT)          // 4096
#define NCTA    148

// Fixed-point quantization: q = rint(x * QS), q = 128*h + l
#define QS      16256.0f
#define C1      (50.0f * 16384.0f / (QS * QS))   // weight of h.h accumulator
#define C2      (50.0f * 128.0f   / (QS * QS))   // weight of (h.l + l.h) accumulator

// SMEM tile geometry: 128 rows x 128 int8, padded row stride 144 bytes
#define SROW    144
#define TB      (128 * SROW)       // 18432 bytes per tile
#define OFF_A_HI  0
#define OFF_A_LO  TB
#define OFF_B(buf, lo)  (2 * TB + (buf) * 2 * TB + (lo) * TB)
#define SMEM_BYTES (6 * TB)        // 110592

// Static device scratch
__device__ int8_t g_ts_hi[NN * DD];
__device__ int8_t g_ts_lo[NN * DD];
__device__ int8_t g_sq_hi[NN * DD];
__device__ int8_t g_sq_lo[NN * DD];
__device__ float  g_rowsum[NN];
__device__ double g_acc[2];

// ---------------- PTX helpers ----------------
__device__ __forceinline__ void cp16(uint32_t saddr, const void* g) {
    asm volatile("cp.async.cg.shared.global [%0], [%1], 16;" :: "r"(saddr), "l"(g));
}
__device__ __forceinline__ void cp_commit() { asm volatile("cp.async.commit_group;"); }
__device__ __forceinline__ void cp_wait0()  { asm volatile("cp.async.wait_group 0;"); }
__device__ __forceinline__ void cp_wait1()  { asm volatile("cp.async.wait_group 1;"); }

__device__ __forceinline__ void ldsm4(uint32_t a, uint32_t& r0, uint32_t& r1,
                                      uint32_t& r2, uint32_t& r3) {
    asm volatile("ldmatrix.sync.aligned.m8n8.x4.shared.b16 {%0,%1,%2,%3}, [%4];"
                 : "=r"(r0), "=r"(r1), "=r"(r2), "=r"(r3) : "r"(a));
}
__device__ __forceinline__ void imma(int* c, const uint32_t* a, uint32_t b0, uint32_t b1) {
    asm volatile("mma.sync.aligned.m16n8k32.row.col.s32.s8.s8.s32 "
                 "{%0,%1,%2,%3}, {%4,%5,%6,%7}, {%8,%9}, {%0,%1,%2,%3};"
                 : "+r"(c[0]), "+r"(c[1]), "+r"(c[2]), "+r"(c[3])
                 : "r"(a[0]), "r"(a[1]), "r"(a[2]), "r"(a[3]), "r"(b0), "r"(b1));
}

// ---------------- kernel 1: normalize + int8 fixed-point hi/lo split ----------------
__global__ void __launch_bounds__(256) k_norm(const float* __restrict__ ts,
                                              const float* __restrict__ sq) {
    const int tid = threadIdx.x;
    if (blockIdx.x < 8) {   // zero accumulators
        reinterpret_cast<float4*>(g_rowsum)[blockIdx.x * 256 + tid] =
            make_float4(0.f, 0.f, 0.f, 0.f);
        if (blockIdx.x == 0 && tid == 0) { g_acc[0] = 0.0; g_acc[1] = 0.0; }
    }
    int gwarp = blockIdx.x * 8 + (tid >> 5);
    int lane  = tid & 31;
    if (gwarp >= 2 * NN) return;
    const bool is_ts = gwarp < NN;
    const int  n     = is_ts ? gwarp : gwarp - NN;
    const float* src = is_ts ? ts : sq;
    int8_t* dh = is_ts ? g_ts_hi : g_sq_hi;
    int8_t* dl = is_ts ? g_ts_lo : g_sq_lo;

    float4 v = reinterpret_cast<const float4*>(src + (size_t)n * DD)[lane];
    float ss = v.x * v.x + v.y * v.y + v.z * v.z + v.w * v.w;
#pragma unroll
    for (int o = 16; o; o >>= 1) ss += __shfl_xor_sync(0xffffffffu, ss, o);
    float inv = 1.0f / fmaxf(sqrtf(ss), 1e-12f);

    float x[4] = {v.x * inv, v.y * inv, v.z * inv, v.w * inv};
    char hi[4], lo[4];
#pragma unroll
    for (int j = 0; j < 4; ++j) {
        float q = rintf(x[j] * QS);                 // exact integer in fp32
        float h = rintf(q * 0.0078125f);            // q/128, |h| <= 127
        float l = q - 128.0f * h;                   // |l| <= 64, exact
        hi[j] = (char)__float2int_rn(h);
        lo[j] = (char)__float2int_rn(l);
    }
    size_t e = (size_t)n * DD + lane * 4;
    *reinterpret_cast<char4*>(dh + e) = make_char4(hi[0], hi[1], hi[2], hi[3]);
    *reinterpret_cast<char4*>(dl + e) = make_char4(lo[0], lo[1], lo[2], lo[3]);
}

// ---------------- tile loader: gmem int8 [row][128] -> padded smem [128][144B] ----------------
__device__ __forceinline__ void load_tile_async(uint32_t s_dst,
                                                const int8_t* g,
                                                int row0, int tid) {
#pragma unroll
    for (int it = 0; it < 4; ++it) {
        int ch  = tid + it * 256;       // 0..1023 16B chunks
        int r   = ch >> 3;              // row 0..127
        int c16 = ch & 7;               // 16B chunk within row
        cp16(s_dst + (uint32_t)(r * SROW + c16 * 16),
             g + (size_t)(row0 + r) * DD + c16 * 16);
    }
}

// ---------------- kernel 2: persistent IMMA GEMM + exp-sum epilogue ----------------
__global__ void __launch_bounds__(256, 1) k_main() {
    extern __shared__ char sh[];
    const uint32_t tb = (uint32_t)__cvta_generic_to_shared(sh);

    const int tid  = threadIdx.x;
    const int wid  = tid >> 5;
    const int lane = tid & 31;
    const int wy   = wid & 3;          // n block (32 rows)
    const int wx   = wid >> 2;         // m block (64 cols)
    const int qr   = lane >> 2, qc = lane & 3;

    // ldmatrix per-lane byte offsets (within a tile)
    // A (m16k32 per 16-row block): lanes 0-15 -> rows, lane>>4 -> 16B k-half
    const uint32_t offA = (uint32_t)((lane & 15) * SROW + (lane >> 4) * 16);
    // B (n8k32, two 8-col blocks per ldsm.x4):
    //   lanes 0-7: cb0 k0-15, 8-15: cb0 k16-31, 16-23: cb1 k0-15, 24-31: cb1 k16-31
    const uint32_t offB = (uint32_t)(((lane & 7) + (lane >> 4) * 8) * SROW +
                                     ((lane >> 3) & 1) * 16);
    const uint32_t aRow = (uint32_t)(wy * 32 * SROW);
    const uint32_t bRow = (uint32_t)(wx * 64 * SROW);

    const int c  = blockIdx.x;
    const int u0 = (c * NUNITS) / NCTA;
    const int u1 = ((c + 1) * NUNITS) / NCTA;

    int cur_n = -1;

    for (int u = u0; u < u1; ++u) {
        const int n   = u >> 6;
        const int m   = u & 63;
        const int buf = u & 1;

        if (n != cur_n) {
            __syncthreads();           // everyone done with old tiles
            load_tile_async(tb + OFF_A_HI, g_ts_hi, n * BT, tid);
            load_tile_async(tb + OFF_A_LO, g_ts_lo, n * BT, tid);
            load_tile_async(tb + OFF_B(buf, 0), g_sq_hi, m * BT, tid);
            load_tile_async(tb + OFF_B(buf, 1), g_sq_lo, m * BT, tid);
            cp_commit();
            cp_wait0();
            cur_n = n;
        }
        // prefetch next unit's B (same n only)
        if (u + 1 < u1 && ((u + 1) >> 6) == n) {
            const int mn = (u + 1) & 63;
            load_tile_async(tb + OFF_B(buf ^ 1, 0), g_sq_hi, mn * BT, tid);
            load_tile_async(tb + OFF_B(buf ^ 1, 1), g_sq_lo, mn * BT, tid);
        }
        cp_commit();
        cp_wait1();
        __syncthreads();

        const uint32_t aHi = tb + OFF_A_HI + aRow + offA;
        const uint32_t aLo = tb + OFF_A_LO + aRow + offA;
        const uint32_t bHi = tb + OFF_B(buf, 0) + bRow + offB;
        const uint32_t bLo = tb + OFF_B(buf, 1) + bRow + offB;

        int accH[2][8][4], accM[2][8][4];
#pragma unroll
        for (int i = 0; i < 2; ++i)
#pragma unroll
            for (int cb = 0; cb < 8; ++cb)
#pragma unroll
                for (int r = 0; r < 4; ++r) { accH[i][cb][r] = 0; accM[i][cb][r] = 0; }

#pragma unroll
        for (int kk = 0; kk < 4; ++kk) {            // K=128 in 4 chunks of 32
            const uint32_t ko = (uint32_t)(kk * 32);
            uint32_t aH[2][4], aL[2][4];
#pragma unroll
            for (int i = 0; i < 2; ++i) {
                ldsm4(aHi + i * (16 * SROW) + ko, aH[i][0], aH[i][1], aH[i][2], aH[i][3]);
                ldsm4(aLo + i * (16 * SROW) + ko, aL[i][0], aL[i][1], aL[i][2], aL[i][3]);
            }
#pragma unroll
            for (int j = 0; j < 4; ++j) {           // 2 col-blocks per iteration
                uint32_t bh0, bh1, bh2, bh3, bl0, bl1, bl2, bl3;
                ldsm4(bHi + j * (16 * SROW) + ko, bh0, bh1, bh2, bh3);
                ldsm4(bLo + j * (16 * SROW) + ko, bl0, bl1, bl2, bl3);
#pragma unroll
                for (int i = 0; i < 2; ++i) {
                    imma(accH[i][2 * j],     aH[i], bh0, bh1);
                    imma(accM[i][2 * j],     aH[i], bl0, bl1);
                    imma(accM[i][2 * j],     aL[i], bh0, bh1);
                    imma(accH[i][2 * j + 1], aH[i], bh2, bh3);
                    imma(accM[i][2 * j + 1], aH[i], bl2, bl3);
                    imma(accM[i][2 * j + 1], aL[i], bh2, bh3);
                }
            }
        }

        // Epilogue: logit-50 = h*C1 + m*C2 - 50; exp-sum, quad reduce, atomic
#pragma unroll
        for (int i = 0; i < 2; ++i) {
            float s0 = 0.f, s1 = 0.f;
#pragma unroll
            for (int cb = 0; cb < 8; ++cb) {
                s0 += __expf(fmaf(__int2float_rn(accH[i][cb][0]), C1,
                           fmaf(__int2float_rn(accM[i][cb][0]), C2, -50.0f)));
                s0 += __expf(fmaf(__int2float_rn(accH[i][cb][1]), C1,
                           fmaf(__int2float_rn(accM[i][cb][1]), C2, -50.0f)));
                s1 += __expf(fmaf(__int2float_rn(accH[i][cb][2]), C1,
                           fmaf(__int2float_rn(accM[i][cb][2]), C2, -50.0f)));
                s1 += __expf(fmaf(__int2float_rn(accH[i][cb][3]), C1,
                           fmaf(__int2float_rn(accM[i][cb][3]), C2, -50.0f)));
            }
            s0 += __shfl_xor_sync(0xffffffffu, s0, 1);
            s0 += __shfl_xor_sync(0xffffffffu, s0, 2);
            s1 += __shfl_xor_sync(0xffffffffu, s1, 1);
            s1 += __shfl_xor_sync(0xffffffffu, s1, 2);
            if (qc == 0) {
                int r = n * BT + wy * 32 + i * 16 + qr;
                atomicAdd(&g_rowsum[r], s0);
                atomicAdd(&g_rowsum[r + 8], s1);
            }
        }
        __syncthreads();   // safe to overwrite buffers next iteration
    }
}

// ---------------- kernel 3: diag + lse + masked loss ----------------
__global__ void __launch_bounds__(256) k_final(const int* __restrict__ pmask) {
    __shared__ double s_loss[256];
    __shared__ float  s_pm[256];
    const int tid = threadIdx.x;
    const int n   = blockIdx.x * 256 + tid;

    float d = 0.f;
    const size_t base = (size_t)n * DD;
#pragma unroll 4
    for (int k = 0; k < DD; ++k) {
        float a = fmaf(128.0f, (float)g_ts_hi[base + k], (float)g_ts_lo[base + k]);
        float b = fmaf(128.0f, (float)g_sq_hi[base + k], (float)g_sq_lo[base + k]);
        d += a * b;
    }
    d *= 50.0f / (QS * QS);

    float lse = 50.0f + logf(g_rowsum[n]);
    float pm  = (float)pmask[n];

    s_loss[tid] = (double)(pm * (d - lse));
    s_pm[tid]   = pm;
    __syncthreads();
    for (int o = 128; o; o >>= 1) {
        if (tid < o) { s_loss[tid] += s_loss[tid + o]; s_pm[tid] += s_pm[tid + o]; }
        __syncthreads();
    }
    if (tid == 0) {
        atomicAdd(&g_acc[0], s_loss[0]);
        atomicAdd(&g_acc[1], (double)s_pm[0]);
    }
}

__global__ void k_div(float* out) {
    out[0] = (float)(-g_acc[0] / (g_acc[1] + 1e-6));
}

extern "C" void kernel_launch(void* const* d_in, const int* in_sizes, int n_in,
                              void* d_out, int out_size) {
    const float* ts = (const float*)d_in[0];
    const float* sq = (const float*)d_in[1];
    const int*   pm = (const int*)d_in[3];
    float* out = (float*)d_out;

    cudaFuncSetAttribute(k_main, cudaFuncAttributeMaxDynamicSharedMemorySize, SMEM_BYTES);

    k_norm<<<2048, 256>>>(ts, sq);
    k_main<<<NCTA, 256, SMEM_BYTES>>>();
    k_final<<<NN / 256, 256>>>(pm);
    k_div<<<1, 1>>>(out);
}

// round 7
// speedup vs baseline: 4.2732x; 4.2732x over previous
#include <cuda_runtime.h>
#include <cuda_fp16.h>
#include <cstdint>

// Problem constants
#define NN      8192
#define DD      128
#define BT      128
#define NT      (NN / BT)          // 64
#define NUNITS  (NT * NT)          // 4096
#define NCTA    148
#define SCALE   50.0f

// SMEM tile geometry: 128 rows x 128 fp16, padded row stride 272 bytes
#define SROW    272
#define TB      (128 * SROW)       // 34816 bytes per tile
#define OFF_A     0
#define OFF_B(buf)  (TB + (buf) * TB)
#define SMEM_BYTES (3 * TB)        // 104448

// Static device scratch
__device__ __half g_ts_h[NN * DD];
__device__ __half g_sq_h[NN * DD];
__device__ float  g_ts_f[NN * DD];   // fp32 normalized (exact diag)
__device__ float  g_sq_f[NN * DD];
__device__ float  g_rowsum[NN];
__device__ double g_acc[2];

// ---------------- PTX helpers ----------------
__device__ __forceinline__ void cp16(uint32_t saddr, const void* g) {
    asm volatile("cp.async.cg.shared.global [%0], [%1], 16;" :: "r"(saddr), "l"(g));
}
__device__ __forceinline__ void cp_commit() { asm volatile("cp.async.commit_group;"); }
__device__ __forceinline__ void cp_wait0()  { asm volatile("cp.async.wait_group 0;"); }
__device__ __forceinline__ void cp_wait1()  { asm volatile("cp.async.wait_group 1;"); }

__device__ __forceinline__ void ldsm4(uint32_t a, uint32_t& r0, uint32_t& r1,
                                      uint32_t& r2, uint32_t& r3) {
    asm volatile("ldmatrix.sync.aligned.m8n8.x4.shared.b16 {%0,%1,%2,%3}, [%4];"
                 : "=r"(r0), "=r"(r1), "=r"(r2), "=r"(r3) : "r"(a));
}
__device__ __forceinline__ void mma16816(float* c, const uint32_t* a, uint32_t b0, uint32_t b1) {
    asm volatile("mma.sync.aligned.m16n8k16.row.col.f32.f16.f16.f32 "
                 "{%0,%1,%2,%3}, {%4,%5,%6,%7}, {%8,%9}, {%0,%1,%2,%3};"
                 : "+f"(c[0]), "+f"(c[1]), "+f"(c[2]), "+f"(c[3])
                 : "r"(a[0]), "r"(a[1]), "r"(a[2]), "r"(a[3]), "r"(b0), "r"(b1));
}

// ---------------- kernel 1: normalize -> fp16 (GEMM) + fp32 (diag) ----------------
__global__ void __launch_bounds__(256) k_norm(const float* __restrict__ ts,
                                              const float* __restrict__ sq) {
    const int tid = threadIdx.x;
    if (blockIdx.x < 8) {   // zero accumulators
        reinterpret_cast<float4*>(g_rowsum)[blockIdx.x * 256 + tid] =
            make_float4(0.f, 0.f, 0.f, 0.f);
        if (blockIdx.x == 0 && tid == 0) { g_acc[0] = 0.0; g_acc[1] = 0.0; }
    }
    int gwarp = blockIdx.x * 8 + (tid >> 5);
    int lane  = tid & 31;
    if (gwarp >= 2 * NN) return;
    const bool is_ts = gwarp < NN;
    const int  n     = is_ts ? gwarp : gwarp - NN;
    const float* src = is_ts ? ts : sq;
    __half* dh = is_ts ? g_ts_h : g_sq_h;
    float*  df = is_ts ? g_ts_f : g_sq_f;

    float4 v = reinterpret_cast<const float4*>(src + (size_t)n * DD)[lane];
    float ss = v.x * v.x + v.y * v.y + v.z * v.z + v.w * v.w;
#pragma unroll
    for (int o = 16; o; o >>= 1) ss += __shfl_xor_sync(0xffffffffu, ss, o);
    float inv = 1.0f / fmaxf(sqrtf(ss), 1e-12f);

    float x[4] = {v.x * inv, v.y * inv, v.z * inv, v.w * inv};
    size_t e = (size_t)n * DD + lane * 4;
    *reinterpret_cast<__half2*>(dh + e)     = __floats2half2_rn(x[0], x[1]);
    *reinterpret_cast<__half2*>(dh + e + 2) = __floats2half2_rn(x[2], x[3]);
    *reinterpret_cast<float4*>(df + e)      = make_float4(x[0], x[1], x[2], x[3]);
}

// ---------------- tile loader: gmem fp16 [row][128] -> padded smem [128][272B] ----------------
__device__ __forceinline__ void load_tile_async(uint32_t s_dst,
                                                const __half* g,
                                                int row0, int tid) {
#pragma unroll
    for (int it = 0; it < 8; ++it) {
        int ch  = tid + it * 256;       // 0..2047 16B chunks
        int r   = ch >> 4;              // row 0..127
        int c16 = ch & 15;              // 16B chunk within row
        cp16(s_dst + (uint32_t)(r * SROW + c16 * 16),
             g + (size_t)(row0 + r) * DD + c16 * 8);
    }
}

// ---------------- kernel 2: persistent fp16 mma GEMM + exp-sum epilogue ----------------
__global__ void __launch_bounds__(256, 1) k_main() {
    extern __shared__ char sh[];
    const uint32_t tb = (uint32_t)__cvta_generic_to_shared(sh);

    const int tid  = threadIdx.x;
    const int wid  = tid >> 5;
    const int lane = tid & 31;
    const int wy   = wid & 3;          // n block (32 rows)
    const int wx   = wid >> 2;         // m block (64 cols)
    const int quad = lane >> 3, rw = lane & 7;
    const int qr   = lane >> 2, qc = lane & 3;

    // ldmatrix per-lane offsets (identical to validated R5 layout)
    const uint32_t offA = (uint32_t)(((quad & 1) * 8 + rw) * SROW + (quad >> 1) * 16);
    const uint32_t offB = (uint32_t)(((quad >> 1) * 8 + rw) * SROW + (quad & 1) * 16);
    const uint32_t aRow = (uint32_t)(wy * 32 * SROW);
    const uint32_t bRow = (uint32_t)(wx * 64 * SROW);

    const int c  = blockIdx.x;
    const int u0 = (c * NUNITS) / NCTA;
    const int u1 = ((c + 1) * NUNITS) / NCTA;

    int cur_n = -1;

    for (int u = u0; u < u1; ++u) {
        const int n   = u >> 6;
        const int m   = u & 63;
        const int buf = u & 1;

        if (n != cur_n) {
            __syncthreads();           // everyone done with old tiles
            load_tile_async(tb + OFF_A, g_ts_h, n * BT, tid);
            load_tile_async(tb + OFF_B(buf), g_sq_h, m * BT, tid);
            cp_commit();
            cp_wait0();
            cur_n = n;
        }
        // prefetch next unit's B (same n only)
        if (u + 1 < u1 && ((u + 1) >> 6) == n) {
            const int mn = (u + 1) & 63;
            load_tile_async(tb + OFF_B(buf ^ 1), g_sq_h, mn * BT, tid);
        }
        cp_commit();
        cp_wait1();
        __syncthreads();

        const uint32_t aP = tb + OFF_A + aRow + offA;
        const uint32_t bP = tb + OFF_B(buf) + bRow + offB;

        float acc[2][8][4];
#pragma unroll
        for (int i = 0; i < 2; ++i)
#pragma unroll
            for (int cb = 0; cb < 8; ++cb)
#pragma unroll
                for (int r = 0; r < 4; ++r) acc[i][cb][r] = 0.f;

#pragma unroll
        for (int kk = 0; kk < 8; ++kk) {
            const uint32_t ko = (uint32_t)(kk * 32);
            uint32_t a0[4], a1[4];
            ldsm4(aP + ko, a0[0], a0[1], a0[2], a0[3]);
            ldsm4(aP + 16 * SROW + ko, a1[0], a1[1], a1[2], a1[3]);
#pragma unroll
            for (int j = 0; j < 4; ++j) {
                uint32_t b0, b1, b2, b3;
                ldsm4(bP + j * (16 * SROW) + ko, b0, b1, b2, b3);
                mma16816(acc[0][2 * j],     a0, b0, b1);
                mma16816(acc[1][2 * j],     a1, b0, b1);
                mma16816(acc[0][2 * j + 1], a0, b2, b3);
                mma16816(acc[1][2 * j + 1], a1, b2, b3);
            }
        }

        // Epilogue: exp(50*v - 50), reduce over m within thread, quad, then atomic
#pragma unroll
        for (int i = 0; i < 2; ++i) {
            float s0 = 0.f, s1 = 0.f;
#pragma unroll
            for (int cb = 0; cb < 8; ++cb) {
                s0 += __expf(fmaf(acc[i][cb][0], SCALE, -SCALE));
                s0 += __expf(fmaf(acc[i][cb][1], SCALE, -SCALE));
                s1 += __expf(fmaf(acc[i][cb][2], SCALE, -SCALE));
                s1 += __expf(fmaf(acc[i][cb][3], SCALE, -SCALE));
            }
            s0 += __shfl_xor_sync(0xffffffffu, s0, 1);
            s0 += __shfl_xor_sync(0xffffffffu, s0, 2);
            s1 += __shfl_xor_sync(0xffffffffu, s1, 1);
            s1 += __shfl_xor_sync(0xffffffffu, s1, 2);
            if (qc == 0) {
                int r = n * BT + wy * 32 + i * 16 + qr;
                atomicAdd(&g_rowsum[r], s0);
                atomicAdd(&g_rowsum[r + 8], s1);
            }
        }
        __syncthreads();   // safe to overwrite buffers next iteration
    }
}

// ---------------- kernel 3: exact diag + lse + masked loss ----------------
__global__ void __launch_bounds__(256) k_final(const int* __restrict__ pmask) {
    __shared__ double s_loss[256];
    __shared__ float  s_pm[256];
    const int tid = threadIdx.x;
    const int n   = blockIdx.x * 256 + tid;

    float d = 0.f;
    const size_t base = (size_t)n * DD;
#pragma unroll 8
    for (int k = 0; k < DD; ++k)
        d += g_ts_f[base + k] * g_sq_f[base + k];
    d *= SCALE;

    float lse = SCALE + logf(g_rowsum[n]);
    float pm  = (float)pmask[n];

    s_loss[tid] = (double)(pm * (d - lse));
    s_pm[tid]   = pm;
    __syncthreads();
    for (int o = 128; o; o >>= 1) {
        if (tid < o) { s_loss[tid] += s_loss[tid + o]; s_pm[tid] += s_pm[tid + o]; }
        __syncthreads();
    }
    if (tid == 0) {
        atomicAdd(&g_acc[0], s_loss[0]);
        atomicAdd(&g_acc[1], (double)s_pm[0]);
    }
}

__global__ void k_div(float* out) {
    out[0] = (float)(-g_acc[0] / (g_acc[1] + 1e-6));
}

extern "C" void kernel_launch(void* const* d_in, const int* in_sizes, int n_in,
                              void* d_out, int out_size) {
    const float* ts = (const float*)d_in[0];
    const float* sq = (const float*)d_in[1];
    const int*   pm = (const int*)d_in[3];
    float* out = (float*)d_out;

    cudaFuncSetAttribute(k_main, cudaFuncAttributeMaxDynamicSharedMemorySize, SMEM_BYTES);

    k_norm<<<2048, 256>>>(ts, sq);
    k_main<<<NCTA, 256, SMEM_BYTES>>>();
    k_final<<<NN / 256, 256>>>(pm);
    k_div<<<1, 1>>>(out);
}

// round 8
// speedup vs baseline: 4.3569x; 1.0196x over previous
#include <cuda_runtime.h>
#include <cuda_fp16.h>
#include <cstdint>

// Problem constants
#define NN      8192
#define DD      128
#define BTN     128                // CTA tile rows (n)
#define BTM     256                // CTA tile cols (m)
#define NTN     (NN / BTN)         // 64
#define NTM     (NN / BTM)         // 32
#define NUNITS  (NTN * NTM)        // 2048
#define NCTA    148
#define SCALE   50.0f

// SMEM geometry: padded row stride 272 bytes (136 fp16)
#define SROW    272
#define TA      (BTN * SROW)       // 34816  (A tile: 128 rows)
#define TBB     (BTM * SROW)       // 69632  (B tile: 256 rows)
#define OFF_A     0
#define OFF_B(buf)  (TA + (buf) * TBB)
#define SMEM_BYTES (TA + 2 * TBB)  // 174080

// Static device scratch
__device__ __half g_ts_h[NN * DD];
__device__ __half g_sq_h[NN * DD];
__device__ float  g_ts_f[NN * DD];   // fp32 normalized (exact diag)
__device__ float  g_sq_f[NN * DD];
__device__ float  g_rowsum[NN];
__device__ double g_acc[2];
__device__ unsigned int g_cnt;

// ---------------- PTX helpers ----------------
__device__ __forceinline__ void cp16(uint32_t saddr, const void* g) {
    asm volatile("cp.async.cg.shared.global [%0], [%1], 16;" :: "r"(saddr), "l"(g));
}
__device__ __forceinline__ void cp_commit() { asm volatile("cp.async.commit_group;"); }
__device__ __forceinline__ void cp_wait0()  { asm volatile("cp.async.wait_group 0;"); }
__device__ __forceinline__ void cp_wait1()  { asm volatile("cp.async.wait_group 1;"); }

__device__ __forceinline__ void ldsm4(uint32_t a, uint32_t& r0, uint32_t& r1,
                                      uint32_t& r2, uint32_t& r3) {
    asm volatile("ldmatrix.sync.aligned.m8n8.x4.shared.b16 {%0,%1,%2,%3}, [%4];"
                 : "=r"(r0), "=r"(r1), "=r"(r2), "=r"(r3) : "r"(a));
}
__device__ __forceinline__ void mma16816(float* c, const uint32_t* a, uint32_t b0, uint32_t b1) {
    asm volatile("mma.sync.aligned.m16n8k16.row.col.f32.f16.f16.f32 "
                 "{%0,%1,%2,%3}, {%4,%5,%6,%7}, {%8,%9}, {%0,%1,%2,%3};"
                 : "+f"(c[0]), "+f"(c[1]), "+f"(c[2]), "+f"(c[3])
                 : "r"(a[0]), "r"(a[1]), "r"(a[2]), "r"(a[3]), "r"(b0), "r"(b1));
}

// ---------------- kernel 1: normalize -> fp16 (GEMM) + fp32 (diag) ----------------
__global__ void __launch_bounds__(256) k_norm(const float* __restrict__ ts,
                                              const float* __restrict__ sq) {
    const int tid = threadIdx.x;
    if (blockIdx.x < 8) {   // zero accumulators
        reinterpret_cast<float4*>(g_rowsum)[blockIdx.x * 256 + tid] =
            make_float4(0.f, 0.f, 0.f, 0.f);
        if (blockIdx.x == 0 && tid == 0) {
            g_acc[0] = 0.0; g_acc[1] = 0.0; g_cnt = 0u;
        }
    }
    int gwarp = blockIdx.x * 8 + (tid >> 5);
    int lane  = tid & 31;
    if (gwarp >= 2 * NN) return;
    const bool is_ts = gwarp < NN;
    const int  n     = is_ts ? gwarp : gwarp - NN;
    const float* src = is_ts ? ts : sq;
    __half* dh = is_ts ? g_ts_h : g_sq_h;
    float*  df = is_ts ? g_ts_f : g_sq_f;

    float4 v = reinterpret_cast<const float4*>(src + (size_t)n * DD)[lane];
    float ss = v.x * v.x + v.y * v.y + v.z * v.z + v.w * v.w;
#pragma unroll
    for (int o = 16; o; o >>= 1) ss += __shfl_xor_sync(0xffffffffu, ss, o);
    float inv = 1.0f / fmaxf(sqrtf(ss), 1e-12f);

    float x[4] = {v.x * inv, v.y * inv, v.z * inv, v.w * inv};
    size_t e = (size_t)n * DD + lane * 4;
    *reinterpret_cast<__half2*>(dh + e)     = __floats2half2_rn(x[0], x[1]);
    *reinterpret_cast<__half2*>(dh + e + 2) = __floats2half2_rn(x[2], x[3]);
    *reinterpret_cast<float4*>(df + e)      = make_float4(x[0], x[1], x[2], x[3]);
}

// ---------------- tile loaders: gmem fp16 [row][128] -> padded smem [r][272B] ----------------
__device__ __forceinline__ void load_A_async(uint32_t s_dst, const __half* g,
                                             int row0, int tid) {
#pragma unroll
    for (int it = 0; it < 8; ++it) {
        int ch  = tid + it * 256;       // 0..2047 16B chunks (128 rows)
        int r   = ch >> 4;
        int c16 = ch & 15;
        cp16(s_dst + (uint32_t)(r * SROW + c16 * 16),
             g + (size_t)(row0 + r) * DD + c16 * 8);
    }
}
__device__ __forceinline__ void load_B_async(uint32_t s_dst, const __half* g,
                                             int row0, int tid) {
#pragma unroll
    for (int it = 0; it < 16; ++it) {
        int ch  = tid + it * 256;       // 0..4095 16B chunks (256 rows)
        int r   = ch >> 4;
        int c16 = ch & 15;
        cp16(s_dst + (uint32_t)(r * SROW + c16 * 16),
             g + (size_t)(row0 + r) * DD + c16 * 8);
    }
}

// ---------------- kernel 2: persistent fp16 mma GEMM + exp-sum epilogue ----------------
__global__ void __launch_bounds__(256, 1) k_main() {
    extern __shared__ char sh[];
    const uint32_t tb = (uint32_t)__cvta_generic_to_shared(sh);

    const int tid  = threadIdx.x;
    const int wid  = tid >> 5;
    const int lane = tid & 31;
    const int wy   = wid & 1;          // n block (64 rows)
    const int wx   = wid >> 1;         // m block (64 cols)
    const int quad = lane >> 3, rw = lane & 7;
    const int qr   = lane >> 2, qc = lane & 3;

    const uint32_t offA = (uint32_t)(((quad & 1) * 8 + rw) * SROW + (quad >> 1) * 16);
    const uint32_t offB = (uint32_t)(((quad >> 1) * 8 + rw) * SROW + (quad & 1) * 16);
    const uint32_t aRow = (uint32_t)(wy * 64 * SROW);
    const uint32_t bRow = (uint32_t)(wx * 64 * SROW);

    const int c  = blockIdx.x;
    const int u0 = (c * NUNITS) / NCTA;
    const int u1 = ((c + 1) * NUNITS) / NCTA;

    int cur_n = -1;

    for (int u = u0; u < u1; ++u) {
        const int n   = u >> 5;        // 32 m-tiles per n
        const int m   = u & 31;
        const int buf = u & 1;

        if (n != cur_n) {
            __syncthreads();
            load_A_async(tb + OFF_A, g_ts_h, n * BTN, tid);
            load_B_async(tb + OFF_B(buf), g_sq_h, m * BTM, tid);
            cp_commit();
            cp_wait0();
            cur_n = n;
        }
        if (u + 1 < u1 && ((u + 1) >> 5) == n) {
            load_B_async(tb + OFF_B(buf ^ 1), g_sq_h, ((u + 1) & 31) * BTM, tid);
        }
        cp_commit();
        cp_wait1();
        __syncthreads();

        const uint32_t aP = tb + OFF_A + aRow + offA;
        const uint32_t bP = tb + OFF_B(buf) + bRow + offB;

        float acc[4][8][4];
#pragma unroll
        for (int i = 0; i < 4; ++i)
#pragma unroll
            for (int cb = 0; cb < 8; ++cb)
#pragma unroll
                for (int r = 0; r < 4; ++r) acc[i][cb][r] = 0.f;

#pragma unroll
        for (int kk = 0; kk < 8; ++kk) {
            const uint32_t ko = (uint32_t)(kk * 32);
            uint32_t a[4][4];
#pragma unroll
            for (int i = 0; i < 4; ++i)
                ldsm4(aP + i * (16 * SROW) + ko, a[i][0], a[i][1], a[i][2], a[i][3]);
#pragma unroll
            for (int j = 0; j < 4; ++j) {
                uint32_t b0, b1, b2, b3;
                ldsm4(bP + j * (16 * SROW) + ko, b0, b1, b2, b3);
#pragma unroll
                for (int i = 0; i < 4; ++i) {
                    mma16816(acc[i][2 * j],     a[i], b0, b1);
                    mma16816(acc[i][2 * j + 1], a[i], b2, b3);
                }
            }
        }

        // Epilogue: exp(50*v - 50), per-thread m-reduce, quad reduce, atomic
#pragma unroll
        for (int i = 0; i < 4; ++i) {
            float s0 = 0.f, s1 = 0.f;
#pragma unroll
            for (int cb = 0; cb < 8; ++cb) {
                s0 += __expf(fmaf(acc[i][cb][0], SCALE, -SCALE));
                s0 += __expf(fmaf(acc[i][cb][1], SCALE, -SCALE));
                s1 += __expf(fmaf(acc[i][cb][2], SCALE, -SCALE));
                s1 += __expf(fmaf(acc[i][cb][3], SCALE, -SCALE));
            }
            s0 += __shfl_xor_sync(0xffffffffu, s0, 1);
            s0 += __shfl_xor_sync(0xffffffffu, s0, 2);
            s1 += __shfl_xor_sync(0xffffffffu, s1, 1);
            s1 += __shfl_xor_sync(0xffffffffu, s1, 2);
            if (qc == 0) {
                int r = n * BTN + wy * 64 + i * 16 + qr;
                atomicAdd(&g_rowsum[r], s0);
                atomicAdd(&g_rowsum[r + 8], s1);
            }
        }
        __syncthreads();
    }
}

// ---------------- kernel 3: exact diag + lse + masked loss (+ fused div) ----------------
__global__ void __launch_bounds__(256) k_final(const int* __restrict__ pmask,
                                               float* __restrict__ out) {
    __shared__ double s_loss[256];
    __shared__ float  s_pm[256];
    __shared__ int    s_last;
    const int tid = threadIdx.x;
    const int n   = blockIdx.x * 256 + tid;

    float d = 0.f;
    const size_t base = (size_t)n * DD;
#pragma unroll 8
    for (int k = 0; k < DD; ++k)
        d += g_ts_f[base + k] * g_sq_f[base + k];
    d *= SCALE;

    float lse = SCALE + logf(g_rowsum[n]);
    float pm  = (float)pmask[n];

    s_loss[tid] = (double)(pm * (d - lse));
    s_pm[tid]   = pm;
    __syncthreads();
    for (int o = 128; o; o >>= 1) {
        if (tid < o) { s_loss[tid] += s_loss[tid + o]; s_pm[tid] += s_pm[tid + o]; }
        __syncthreads();
    }
    if (tid == 0) {
        atomicAdd(&g_acc[0], s_loss[0]);
        atomicAdd(&g_acc[1], (double)s_pm[0]);
        __threadfence();
        unsigned int v = atomicAdd(&g_cnt, 1u);
        s_last = (v == (unsigned int)(gridDim.x - 1)) ? 1 : 0;
    }
    __syncthreads();
    if (s_last && tid == 0)
        out[0] = (float)(-g_acc[0] / (g_acc[1] + 1e-6));
}

extern "C" void kernel_launch(void* const* d_in, const int* in_sizes, int n_in,
                              void* d_out, int out_size) {
    const float* ts = (const float*)d_in[0];
    const float* sq = (const float*)d_in[1];
    const int*   pm = (const int*)d_in[3];
    float* out = (float*)d_out;

    cudaFuncSetAttribute(k_main, cudaFuncAttributeMaxDynamicSharedMemorySize, SMEM_BYTES);

    k_norm<<<2048, 256>>>(ts, sq);
    k_main<<<NCTA, 256, SMEM_BYTES>>>();
    k_final<<<NN / 256, 256>>>(pm, out);
}

// round 9
// speedup vs baseline: 4.3979x; 1.0094x over previous
#include <cuda_runtime.h>
#include <cuda_fp16.h>
#include <cstdint>

// Problem constants
#define NN      8192
#define DD      128
#define BTN     128                // CTA tile rows (n)
#define BTM     256                // CTA tile cols (m)
#define NTN     (NN / BTN)         // 64
#define NTM     (NN / BTM)         // 32
#define NUNITS  (NTN * NTM)        // 2048
#define NCTA    148
#define SCALE   50.0f

// SMEM geometry: padded row stride 272 bytes (136 fp16)
#define SROW    272
#define TA      (BTN * SROW)       // 34816
#define TBB     (BTM * SROW)       // 69632
#define OFF_A     0
#define OFF_B(buf)  (TA + (buf) * TBB)
#define SMEM_BYTES (TA + 2 * TBB)  // 174080

// Static device scratch
__device__ __half g_ts_h[NN * DD];
__device__ __half g_sq_h[NN * DD];
__device__ float  g_ts_f[NN * DD];   // fp32 normalized (exact diag)
__device__ float  g_sq_f[NN * DD];
__device__ float  g_rowsum[NN];
__device__ double g_acc[2];
__device__ unsigned int g_cnt;

// ---------------- PTX helpers ----------------
__device__ __forceinline__ void cp16(uint32_t saddr, const void* g) {
    asm volatile("cp.async.cg.shared.global [%0], [%1], 16;" :: "r"(saddr), "l"(g));
}
__device__ __forceinline__ void cp_commit() { asm volatile("cp.async.commit_group;"); }
__device__ __forceinline__ void cp_wait0()  { asm volatile("cp.async.wait_group 0;"); }
__device__ __forceinline__ void cp_wait1()  { asm volatile("cp.async.wait_group 1;"); }

__device__ __forceinline__ void ldsm4(uint32_t a, uint32_t& r0, uint32_t& r1,
                                      uint32_t& r2, uint32_t& r3) {
    asm volatile("ldmatrix.sync.aligned.m8n8.x4.shared.b16 {%0,%1,%2,%3}, [%4];"
                 : "=r"(r0), "=r"(r1), "=r"(r2), "=r"(r3) : "r"(a));
}
// fp16-accumulate HMMA: D,C are 2x .f16x2 regs
__device__ __forceinline__ void mma16816h(uint32_t* c, const uint32_t* a,
                                          uint32_t b0, uint32_t b1) {
    asm volatile("mma.sync.aligned.m16n8k16.row.col.f16.f16.f16.f16 "
                 "{%0,%1}, {%2,%3,%4,%5}, {%6,%7}, {%0,%1};"
                 : "+r"(c[0]), "+r"(c[1])
                 : "r"(a[0]), "r"(a[1]), "r"(a[2]), "r"(a[3]), "r"(b0), "r"(b1));
}
__device__ __forceinline__ float2 h2_to_f2(uint32_t u) {
    float2 r;
    asm("{\n\t.reg .f16 h0, h1;\n\t"
        "mov.b32 {h0, h1}, %2;\n\t"
        "cvt.f32.f16 %0, h0;\n\t"
        "cvt.f32.f16 %1, h1;\n\t}" : "=f"(r.x), "=f"(r.y) : "r"(u));
    return r;
}

// ---------------- kernel 1: normalize -> fp16 (GEMM) + fp32 (diag) ----------------
__global__ void __launch_bounds__(256) k_norm(const float* __restrict__ ts,
                                              const float* __restrict__ sq) {
    const int tid = threadIdx.x;
    if (blockIdx.x < 8) {   // zero accumulators
        reinterpret_cast<float4*>(g_rowsum)[blockIdx.x * 256 + tid] =
            make_float4(0.f, 0.f, 0.f, 0.f);
        if (blockIdx.x == 0 && tid == 0) {
            g_acc[0] = 0.0; g_acc[1] = 0.0; g_cnt = 0u;
        }
    }
    int gwarp = blockIdx.x * 8 + (tid >> 5);
    int lane  = tid & 31;
    if (gwarp >= 2 * NN) return;
    const bool is_ts = gwarp < NN;
    const int  n     = is_ts ? gwarp : gwarp - NN;
    const float* src = is_ts ? ts : sq;
    __half* dh = is_ts ? g_ts_h : g_sq_h;
    float*  df = is_ts ? g_ts_f : g_sq_f;

    float4 v = reinterpret_cast<const float4*>(src + (size_t)n * DD)[lane];
    float ss = v.x * v.x + v.y * v.y + v.z * v.z + v.w * v.w;
#pragma unroll
    for (int o = 16; o; o >>= 1) ss += __shfl_xor_sync(0xffffffffu, ss, o);
    float inv = 1.0f / fmaxf(sqrtf(ss), 1e-12f);

    float x[4] = {v.x * inv, v.y * inv, v.z * inv, v.w * inv};
    size_t e = (size_t)n * DD + lane * 4;
    *reinterpret_cast<__half2*>(dh + e)     = __floats2half2_rn(x[0], x[1]);
    *reinterpret_cast<__half2*>(dh + e + 2) = __floats2half2_rn(x[2], x[3]);
    *reinterpret_cast<float4*>(df + e)      = make_float4(x[0], x[1], x[2], x[3]);
}

// ---------------- tile loaders ----------------
__device__ __forceinline__ void load_A_async(uint32_t s_dst, const __half* g,
                                             int row0, int tid) {
#pragma unroll
    for (int it = 0; it < 8; ++it) {
        int ch  = tid + it * 256;
        int r   = ch >> 4;
        int c16 = ch & 15;
        cp16(s_dst + (uint32_t)(r * SROW + c16 * 16),
             g + (size_t)(row0 + r) * DD + c16 * 8);
    }
}
__device__ __forceinline__ void load_B_async(uint32_t s_dst, const __half* g,
                                             int row0, int tid) {
#pragma unroll
    for (int it = 0; it < 16; ++it) {
        int ch  = tid + it * 256;
        int r   = ch >> 4;
        int c16 = ch & 15;
        cp16(s_dst + (uint32_t)(r * SROW + c16 * 16),
             g + (size_t)(row0 + r) * DD + c16 * 8);
    }
}

// process 1/8 of the previous unit's accumulators: i = kk>>1, 4 col-blocks
#define PREV_CHUNK(kk)                                                         \
    {                                                                          \
        const int pi = (kk) >> 1, pc0 = ((kk) & 1) * 4;                        \
        _Pragma("unroll")                                                      \
        for (int cb = 0; cb < 4; ++cb) {                                       \
            float2 lo = h2_to_f2(accP[pi][pc0 + cb][0]);                       \
            float2 hi = h2_to_f2(accP[pi][pc0 + cb][1]);                       \
            sums[pi][0] += __expf(fmaf(lo.x, SCALE, -SCALE));                  \
            sums[pi][0] += __expf(fmaf(lo.y, SCALE, -SCALE));                  \
            sums[pi][1] += __expf(fmaf(hi.x, SCALE, -SCALE));                  \
            sums[pi][1] += __expf(fmaf(hi.y, SCALE, -SCALE));                  \
        }                                                                      \
    }

// ---------------- kernel 2: persistent fp16 mma GEMM, pipelined epilogue ----------------
__global__ void __launch_bounds__(256, 1) k_main() {
    extern __shared__ char sh[];
    const uint32_t tb = (uint32_t)__cvta_generic_to_shared(sh);

    const int tid  = threadIdx.x;
    const int lane = tid & 31;
    const int wid  = tid >> 5;
    const int wy   = wid & 1;          // n block (64 rows)
    const int wx   = wid >> 1;         // m block (64 cols)
    const int quad = lane >> 3, rw = lane & 7;
    const int qr   = lane >> 2, qc = lane & 3;

    const uint32_t offA = (uint32_t)(((quad & 1) * 8 + rw) * SROW + (quad >> 1) * 16);
    const uint32_t offB = (uint32_t)(((quad >> 1) * 8 + rw) * SROW + (quad & 1) * 16);
    const uint32_t aRow = (uint32_t)(wy * 64 * SROW);
    const uint32_t bRow = (uint32_t)(wx * 64 * SROW);

    const int c  = blockIdx.x;
    const int u0 = (c * NUNITS) / NCTA;
    const int u1 = ((c + 1) * NUNITS) / NCTA;

    // previous-unit accumulators (half2 pairs); -2.0h -> exp(-150) = 0
    uint32_t accP[4][8][2];
#pragma unroll
    for (int i = 0; i < 4; ++i)
#pragma unroll
        for (int cb = 0; cb < 8; ++cb) {
            accP[i][cb][0] = 0xC000C000u; accP[i][cb][1] = 0xC000C000u;
        }
    float sums[4][2];
#pragma unroll
    for (int i = 0; i < 4; ++i) { sums[i][0] = 0.f; sums[i][1] = 0.f; }

    int cur_n = -1;
    int n_prev = u0 >> 5;              // harmless target for the zero flush

    for (int u = u0; u < u1; ++u) {
        const int n   = u >> 5;
        const int m   = u & 31;
        const int buf = u & 1;

        if (n != cur_n) {
            __syncthreads();
            load_A_async(tb + OFF_A, g_ts_h, n * BTN, tid);
            load_B_async(tb + OFF_B(buf), g_sq_h, m * BTM, tid);
            cp_commit();
            cp_wait0();
            cur_n = n;
        }
        if (u + 1 < u1 && ((u + 1) >> 5) == n) {
            load_B_async(tb + OFF_B(buf ^ 1), g_sq_h, ((u + 1) & 31) * BTM, tid);
        }
        cp_commit();
        cp_wait1();
        __syncthreads();

        const uint32_t aP = tb + OFF_A + aRow + offA;
        const uint32_t bP = tb + OFF_B(buf) + bRow + offB;

        uint32_t accC[4][8][2];
#pragma unroll
        for (int i = 0; i < 4; ++i)
#pragma unroll
            for (int cb = 0; cb < 8; ++cb) { accC[i][cb][0] = 0u; accC[i][cb][1] = 0u; }

#pragma unroll
        for (int kk = 0; kk < 8; ++kk) {
            const uint32_t ko = (uint32_t)(kk * 32);
            uint32_t a[4][4];
#pragma unroll
            for (int i = 0; i < 4; ++i)
                ldsm4(aP + i * (16 * SROW) + ko, a[i][0], a[i][1], a[i][2], a[i][3]);
#pragma unroll
            for (int j = 0; j < 4; ++j) {
                uint32_t b0, b1, b2, b3;
                ldsm4(bP + j * (16 * SROW) + ko, b0, b1, b2, b3);
#pragma unroll
                for (int i = 0; i < 4; ++i) {
                    mma16816h(accC[i][2 * j],     a[i], b0, b1);
                    mma16816h(accC[i][2 * j + 1], a[i], b2, b3);
                }
            }
            // interleave previous unit's exp work into the MMA shadow
            PREV_CHUNK(kk);
        }

        // flush previous unit's row sums
#pragma unroll
        for (int i = 0; i < 4; ++i) {
            float s0 = sums[i][0], s1 = sums[i][1];
            s0 += __shfl_xor_sync(0xffffffffu, s0, 1);
            s0 += __shfl_xor_sync(0xffffffffu, s0, 2);
            s1 += __shfl_xor_sync(0xffffffffu, s1, 1);
            s1 += __shfl_xor_sync(0xffffffffu, s1, 2);
            if (qc == 0) {
                int r = n_prev * BTN + wy * 64 + i * 16 + qr;
                atomicAdd(&g_rowsum[r], s0);
                atomicAdd(&g_rowsum[r + 8], s1);
            }
            sums[i][0] = 0.f; sums[i][1] = 0.f;
        }
        n_prev = n;
#pragma unroll
        for (int i = 0; i < 4; ++i)
#pragma unroll
            for (int cb = 0; cb < 8; ++cb) {
                accP[i][cb][0] = accC[i][cb][0];
                accP[i][cb][1] = accC[i][cb][1];
            }
        __syncthreads();
    }

    // drain: last unit's accumulators
#pragma unroll
    for (int kk = 0; kk < 8; ++kk) PREV_CHUNK(kk);
#pragma unroll
    for (int i = 0; i < 4; ++i) {
        float s0 = sums[i][0], s1 = sums[i][1];
        s0 += __shfl_xor_sync(0xffffffffu, s0, 1);
        s0 += __shfl_xor_sync(0xffffffffu, s0, 2);
        s1 += __shfl_xor_sync(0xffffffffu, s1, 1);
        s1 += __shfl_xor_sync(0xffffffffu, s1, 2);
        if (qc == 0) {
            int r = n_prev * BTN + wy * 64 + i * 16 + qr;
            atomicAdd(&g_rowsum[r], s0);
            atomicAdd(&g_rowsum[r + 8], s1);
        }
    }
}

// ---------------- kernel 3: exact diag + lse + masked loss (+ fused div) ----------------
__global__ void __launch_bounds__(256) k_final(const int* __restrict__ pmask,
                                               float* __restrict__ out) {
    __shared__ double s_loss[256];
    __shared__ float  s_pm[256];
    __shared__ int    s_last;
    const int tid = threadIdx.x;
    const int n   = blockIdx.x * 256 + tid;

    float d = 0.f;
    const size_t base = (size_t)n * DD;
#pragma unroll 8
    for (int k = 0; k < DD; ++k)
        d += g_ts_f[base + k] * g_sq_f[base + k];
    d *= SCALE;

    float lse = SCALE + logf(g_rowsum[n]);
    float pm  = (float)pmask[n];

    s_loss[tid] = (double)(pm * (d - lse));
    s_pm[tid]   = pm;
    __syncthreads();
    for (int o = 128; o; o >>= 1) {
        if (tid < o) { s_loss[tid] += s_loss[tid + o]; s_pm[tid] += s_pm[tid + o]; }
        __syncthreads();
    }
    if (tid == 0) {
        atomicAdd(&g_acc[0], s_loss[0]);
        atomicAdd(&g_acc[1], (double)s_pm[0]);
        __threadfence();
        unsigned int v = atomicAdd(&g_cnt, 1u);
        s_last = (v == (unsigned int)(gridDim.x - 1)) ? 1 : 0;
    }
    __syncthreads();
    if (s_last && tid == 0)
        out[0] = (float)(-g_acc[0] / (g_acc[1] + 1e-6));
}

extern "C" void kernel_launch(void* const* d_in, const int* in_sizes, int n_in,
                              void* d_out, int out_size) {
    const float* ts = (const float*)d_in[0];
    const float* sq = (const float*)d_in[1];
    const int*   pm = (const int*)d_in[3];
    float* out = (float*)d_out;

    cudaFuncSetAttribute(k_main, cudaFuncAttributeMaxDynamicSharedMemorySize, SMEM_BYTES);

    k_norm<<<2048, 256>>>(ts, sq);
    k_main<<<NCTA, 256, SMEM_BYTES>>>();
    k_final<<<NN / 256, 256>>>(pm, out);
}